// round 1
// baseline (speedup 1.0000x reference)
#include <cuda_runtime.h>
#include <math.h>

#define NSEQ 8192
#define VTOK 25
#define DM   256
#define NH   8
#define HD   32
#define D3   768
#define DF   1024

// smem layout (floats): s_res[25*256] | s_y[25*256] | s_work[25*1024]
#define S_RES  0
#define S_Y    6400
#define S_WORK 12800
#define SMEM_FLOATS (12800 + 25600)

__global__ __launch_bounds__(256, 1)
void spatial_block_kernel(
    const float* __restrict__ x,
    const float* __restrict__ ln1_g, const float* __restrict__ ln1_b,
    const float* __restrict__ qkv_w, const float* __restrict__ qkv_b,
    const float* __restrict__ proj_w, const float* __restrict__ proj_b,
    const float* __restrict__ logit_scale,
    const float* __restrict__ ln2_g, const float* __restrict__ ln2_b,
    const float* __restrict__ ffn_w1, const float* __restrict__ ffn_b1,
    const float* __restrict__ ffn_w2, const float* __restrict__ ffn_b2,
    float* __restrict__ out)
{
    extern __shared__ float sm[];
    float* s_res  = sm + S_RES;
    float* s_y    = sm + S_Y;
    float* s_work = sm + S_WORK;

    const int n    = blockIdx.x;
    const int tid  = threadIdx.x;
    const int lane = tid & 31;
    const int wid  = tid >> 5;
    const float* xg = x + (size_t)n * (VTOK * DM);

    // ---- load x tile into smem (residual) ----
    {
        const float4* src = (const float4*)xg;
        float4* dst = (float4*)s_res;
        #pragma unroll
        for (int i = tid; i < VTOK * DM / 4; i += 256) dst[i] = src[i];
    }
    __syncthreads();

    // ---- LN1: s_res -> s_y ----
    for (int r = wid; r < VTOK; r += 8) {
        float s = 0.f, s2 = 0.f;
        #pragma unroll
        for (int j = 0; j < 8; j++) {
            float v = s_res[r * DM + lane + 32 * j];
            s += v; s2 += v * v;
        }
        #pragma unroll
        for (int o = 16; o > 0; o >>= 1) {
            s  += __shfl_xor_sync(0xffffffffu, s,  o);
            s2 += __shfl_xor_sync(0xffffffffu, s2, o);
        }
        float mean = s * (1.f / DM);
        float var  = s2 * (1.f / DM) - mean * mean;
        float inv  = rsqrtf(var + 1e-5f);
        #pragma unroll
        for (int j = 0; j < 8; j++) {
            int c = lane + 32 * j;
            s_y[r * DM + c] = (s_res[r * DM + c] - mean) * inv * ln1_g[c] + ln1_b[c];
        }
    }
    __syncthreads();

    // ---- QKV: s_work[r][c] = sum_k s_y[r][k] * qkv_w[k][c] + b,  c in [0,768) ----
    #pragma unroll
    for (int cc = 0; cc < 3; cc++) {
        int c = cc * 256 + tid;
        float acc[VTOK];
        float bv = qkv_b[c];
        #pragma unroll
        for (int r = 0; r < VTOK; r++) acc[r] = bv;
        #pragma unroll 4
        for (int k = 0; k < DM; k += 2) {
            float w0 = qkv_w[(size_t)k * D3 + c];
            float w1 = qkv_w[(size_t)(k + 1) * D3 + c];
            #pragma unroll
            for (int r = 0; r < VTOK; r++) {
                float2 yv = *(const float2*)(s_y + r * DM + k);
                acc[r] = fmaf(yv.x, w0, acc[r]);
                acc[r] = fmaf(yv.y, w1, acc[r]);
            }
        }
        #pragma unroll
        for (int r = 0; r < VTOK; r++) s_work[r * D3 + c] = acc[r];
    }
    __syncthreads();

    // ---- cosine attention: warp = head, lane = query row; out -> s_y[r][h*32+d] ----
    {
        const int h = wid;
        const int i = lane;
        const int ri = (i < VTOK) ? i : 0;  // clamp dead lanes to valid data
        const float* qb = s_work + h * HD;
        const float* kb = s_work + DM + h * HD;
        const float* vb = s_work + 2 * DM + h * HD;

        float q[HD];
        #pragma unroll
        for (int d = 0; d < HD; d++) q[d] = qb[ri * D3 + d];
        float qn2 = 0.f;
        #pragma unroll
        for (int d = 0; d < HD; d++) qn2 = fmaf(q[d], q[d], qn2);
        float kn2 = 0.f;
        #pragma unroll
        for (int d = 0; d < HD; d++) { float kv = kb[ri * D3 + d]; kn2 = fmaf(kv, kv, kn2); }
        float inv_kn = 1.f / fmaxf(sqrtf(kn2), 1e-12f);

        float sc   = expf(fminf(logit_scale[h], 4.6051701859880913680f));   // clamp at log(100)
        float coef = sc * (1.f / fmaxf(sqrtf(qn2), 1e-12f)) * 0.17677669529663688110f; // 1/sqrt(32)

        float lg[VTOK];
        #pragma unroll
        for (int j = 0; j < VTOK; j++) {
            float ikn = __shfl_sync(0xffffffffu, inv_kn, j);
            float dot = 0.f;
            #pragma unroll
            for (int d = 0; d < HD; d++) dot = fmaf(q[d], kb[j * D3 + d], dot);
            lg[j] = dot * coef * ikn;
        }
        float m = lg[0];
        #pragma unroll
        for (int j = 1; j < VTOK; j++) m = fmaxf(m, lg[j]);
        float ssum = 0.f;
        #pragma unroll
        for (int j = 0; j < VTOK; j++) { lg[j] = expf(lg[j] - m); ssum += lg[j]; }
        float rs = 1.f / ssum;

        float o[HD];
        #pragma unroll
        for (int d = 0; d < HD; d++) o[d] = 0.f;
        #pragma unroll
        for (int j = 0; j < VTOK; j++) {
            float p = lg[j] * rs;
            #pragma unroll
            for (int d = 0; d < HD; d++) o[d] = fmaf(p, vb[j * D3 + d], o[d]);
        }
        if (i < VTOK) {
            #pragma unroll
            for (int d = 0; d < HD; d++) s_y[i * DM + h * HD + d] = o[d];
        }
    }
    __syncthreads();

    // ---- proj + residual: s_res += s_y @ proj_w + b ----
    {
        int c = tid;
        float acc[VTOK];
        float bv = proj_b[c];
        #pragma unroll
        for (int r = 0; r < VTOK; r++) acc[r] = bv;
        #pragma unroll 4
        for (int k = 0; k < DM; k += 2) {
            float w0 = proj_w[(size_t)k * DM + c];
            float w1 = proj_w[(size_t)(k + 1) * DM + c];
            #pragma unroll
            for (int r = 0; r < VTOK; r++) {
                float2 yv = *(const float2*)(s_y + r * DM + k);
                acc[r] = fmaf(yv.x, w0, acc[r]);
                acc[r] = fmaf(yv.y, w1, acc[r]);
            }
        }
        #pragma unroll
        for (int r = 0; r < VTOK; r++) s_res[r * DM + c] += acc[r];
    }
    __syncthreads();

    // ---- LN2: s_res -> s_y ----
    for (int r = wid; r < VTOK; r += 8) {
        float s = 0.f, s2 = 0.f;
        #pragma unroll
        for (int j = 0; j < 8; j++) {
            float v = s_res[r * DM + lane + 32 * j];
            s += v; s2 += v * v;
        }
        #pragma unroll
        for (int o = 16; o > 0; o >>= 1) {
            s  += __shfl_xor_sync(0xffffffffu, s,  o);
            s2 += __shfl_xor_sync(0xffffffffu, s2, o);
        }
        float mean = s * (1.f / DM);
        float var  = s2 * (1.f / DM) - mean * mean;
        float inv  = rsqrtf(var + 1e-5f);
        #pragma unroll
        for (int j = 0; j < 8; j++) {
            int c = lane + 32 * j;
            s_y[r * DM + c] = (s_res[r * DM + c] - mean) * inv * ln2_g[c] + ln2_b[c];
        }
    }
    __syncthreads();

    // ---- FFN1 + exact GELU: s_work[r][c] = gelu(s_y @ ffn_w1 + b1), c in [0,1024) ----
    #pragma unroll
    for (int cc = 0; cc < 4; cc++) {
        int c = cc * 256 + tid;
        float acc[VTOK];
        float bv = ffn_b1[c];
        #pragma unroll
        for (int r = 0; r < VTOK; r++) acc[r] = bv;
        #pragma unroll 4
        for (int k = 0; k < DM; k += 2) {
            float w0 = ffn_w1[(size_t)k * DF + c];
            float w1 = ffn_w1[(size_t)(k + 1) * DF + c];
            #pragma unroll
            for (int r = 0; r < VTOK; r++) {
                float2 yv = *(const float2*)(s_y + r * DM + k);
                acc[r] = fmaf(yv.x, w0, acc[r]);
                acc[r] = fmaf(yv.y, w1, acc[r]);
            }
        }
        #pragma unroll
        for (int r = 0; r < VTOK; r++) {
            float v = acc[r];
            s_work[r * DF + c] = 0.5f * v * (1.f + erff(v * 0.70710678118654752440f));
        }
    }
    __syncthreads();

    // ---- FFN2 + residual -> gmem out ----
    {
        int c = tid;
        float acc[VTOK];
        float bv = ffn_b2[c];
        #pragma unroll
        for (int r = 0; r < VTOK; r++) acc[r] = bv;
        #pragma unroll 4
        for (int k = 0; k < DF; k += 2) {
            float w0 = ffn_w2[(size_t)k * DM + c];
            float w1 = ffn_w2[(size_t)(k + 1) * DM + c];
            #pragma unroll
            for (int r = 0; r < VTOK; r++) {
                float2 hv = *(const float2*)(s_work + r * DF + k);
                acc[r] = fmaf(hv.x, w0, acc[r]);
                acc[r] = fmaf(hv.y, w1, acc[r]);
            }
        }
        float* og = out + (size_t)n * (VTOK * DM);
        #pragma unroll
        for (int r = 0; r < VTOK; r++) og[r * DM + c] = s_res[r * DM + c] + acc[r];
    }
}

extern "C" void kernel_launch(void* const* d_in, const int* in_sizes, int n_in,
                              void* d_out, int out_size)
{
    const float* x      = (const float*)d_in[0];
    const float* ln1_g  = (const float*)d_in[1];
    const float* ln1_b  = (const float*)d_in[2];
    const float* qkv_w  = (const float*)d_in[3];
    const float* qkv_b  = (const float*)d_in[4];
    const float* proj_w = (const float*)d_in[5];
    const float* proj_b = (const float*)d_in[6];
    const float* lscale = (const float*)d_in[7];
    const float* ln2_g  = (const float*)d_in[8];
    const float* ln2_b  = (const float*)d_in[9];
    const float* ffn_w1 = (const float*)d_in[10];
    const float* ffn_b1 = (const float*)d_in[11];
    const float* ffn_w2 = (const float*)d_in[12];
    const float* ffn_b2 = (const float*)d_in[13];
    float* out = (float*)d_out;

    size_t smem = SMEM_FLOATS * sizeof(float);
    cudaFuncSetAttribute(spatial_block_kernel,
                         cudaFuncAttributeMaxDynamicSharedMemorySize, (int)smem);
    spatial_block_kernel<<<NSEQ, 256, smem>>>(
        x, ln1_g, ln1_b, qkv_w, qkv_b, proj_w, proj_b, lscale,
        ln2_g, ln2_b, ffn_w1, ffn_b1, ffn_w2, ffn_b2, out);
}

// round 4
// speedup vs baseline: 2.5108x; 2.5108x over previous
#include <cuda_runtime.h>
#include <math.h>
#include <stdint.h>

#define NSEQ  8192
#define VTOK  25
#define DM    256
#define NH    8
#define HD    32
#define DF    1024
#define LDA   260          // padded row stride for GEMM-A smem buffers (conflict-free frags)
#define LDQ   196          // row stride for qkv head-pair chunk buffer
#define NCTA  (NSEQ/2)

#define QKV_OFF  0
#define PROJ_OFF 196608
#define F1_OFF   262144
#define F2_OFF   524288
#define WTOT     786432

__device__ float g_wr[WTOT];   // tf32-rounded weights

__device__ __forceinline__ float tf32r(float x) {
    uint32_t u; asm("cvt.rna.tf32.f32 %0, %1;" : "=r"(u) : "f"(x));
    return __uint_as_float(u);
}
__device__ __forceinline__ float gelu_exact(float v) {
    return 0.5f * v * (1.f + erff(v * 0.70710678118654752440f));
}

__global__ void prep_kernel(const float* __restrict__ qkv_w, const float* __restrict__ proj_w,
                            const float* __restrict__ f1,    const float* __restrict__ f2) {
    int i = blockIdx.x * 256 + threadIdx.x;
    if (i >= WTOT) return;
    float v;
    if      (i < PROJ_OFF) v = qkv_w[i];
    else if (i < F1_OFF)   v = proj_w[i - PROJ_OFF];
    else if (i < F2_OFF)   v = f1[i - F1_OFF];
    else                   v = f2[i - F2_OFF];
    g_wr[i] = tf32r(v);
}

#define MMA_TF32(D, A, B0, B1)                                              \
    asm("mma.sync.aligned.m16n8k8.row.col.f32.tf32.tf32.f32 "               \
        "{%0,%1,%2,%3}, {%4,%5,%6,%7}, {%8,%9}, {%0,%1,%2,%3};"             \
        : "+f"(D[0]), "+f"(D[1]), "+f"(D[2]), "+f"(D[3])                    \
        : "r"(A[0]), "r"(A[1]), "r"(A[2]), "r"(A[3]), "r"(B0), "r"(B1))

// Warp computes a 32xNT*8 C tile: A (smem, stride LDA, rows m_base..m_base+31 via Asm ptr),
// B from gmem (tf32-rounded), per-tile column offsets coff[]. B double-buffered in regs.
template<int NT, int K>
__device__ __forceinline__ void gemm_sg(const float* __restrict__ Asm,
                                        const float* __restrict__ Bg, int ldb,
                                        const int (&coff)[NT],
                                        float (&acc)[2][NT][4], int g, int t4)
{
    const float* a0p = Asm + g * LDA + t4;
    const float* a1p = Asm + (16 + g) * LDA + t4;
    const float* bb  = Bg + t4 * ldb + g;
    uint32_t bc[NT][2];
    #pragma unroll
    for (int nt = 0; nt < NT; nt++) {
        bc[nt][0] = __float_as_uint(bb[coff[nt]]);
        bc[nt][1] = __float_as_uint(bb[4 * ldb + coff[nt]]);
    }
    #pragma unroll 4
    for (int k0 = 0; k0 < K; k0 += 8) {
        uint32_t a0[4], a1[4];
        a0[0] = __float_as_uint(a0p[k0]);            a0[1] = __float_as_uint(a0p[8 * LDA + k0]);
        a0[2] = __float_as_uint(a0p[k0 + 4]);        a0[3] = __float_as_uint(a0p[8 * LDA + k0 + 4]);
        a1[0] = __float_as_uint(a1p[k0]);            a1[1] = __float_as_uint(a1p[8 * LDA + k0]);
        a1[2] = __float_as_uint(a1p[k0 + 4]);        a1[3] = __float_as_uint(a1p[8 * LDA + k0 + 4]);
        uint32_t bn[NT][2];
        if (k0 < K - 8) {
            const float* bk = bb + (k0 + 8) * ldb;
            #pragma unroll
            for (int nt = 0; nt < NT; nt++) {
                bn[nt][0] = __float_as_uint(bk[coff[nt]]);
                bn[nt][1] = __float_as_uint(bk[4 * ldb + coff[nt]]);
            }
        }
        #pragma unroll
        for (int nt = 0; nt < NT; nt++) {
            MMA_TF32(acc[0][nt], a0, bc[nt][0], bc[nt][1]);
            MMA_TF32(acc[1][nt], a1, bc[nt][0], bc[nt][1]);
        }
        if (k0 < K - 8) {
            #pragma unroll
            for (int nt = 0; nt < NT; nt++) { bc[nt][0] = bn[nt][0]; bc[nt][1] = bn[nt][1]; }
        }
    }
}

__device__ __forceinline__ void ln_row(const float* __restrict__ src, float* __restrict__ dst,
                                       const float* __restrict__ gg, const float* __restrict__ bb,
                                       int lane)
{
    float v[8], s = 0.f, s2 = 0.f;
    #pragma unroll
    for (int j = 0; j < 8; j++) { v[j] = src[lane + 32 * j]; s += v[j]; s2 += v[j] * v[j]; }
    #pragma unroll
    for (int o = 16; o > 0; o >>= 1) {
        s  += __shfl_xor_sync(0xffffffffu, s,  o);
        s2 += __shfl_xor_sync(0xffffffffu, s2, o);
    }
    float mean = s * (1.f / DM);
    float var  = s2 * (1.f / DM) - mean * mean;
    float inv  = rsqrtf(var + 1e-5f);
    #pragma unroll
    for (int j = 0; j < 8; j++) {
        int c = lane + 32 * j;
        dst[c] = tf32r((v[j] - mean) * inv * gg[c] + bb[c]);
    }
}

__global__ __launch_bounds__(256, 1)
void spatial_block_mma(
    const float* __restrict__ x,
    const float* __restrict__ ln1_g, const float* __restrict__ ln1_b,
    const float* __restrict__ qkv_b,
    const float* __restrict__ proj_b,
    const float* __restrict__ logit_scale,
    const float* __restrict__ ln2_g, const float* __restrict__ ln2_b,
    const float* __restrict__ ffn_b1, const float* __restrict__ ffn_b2,
    float* __restrict__ out)
{
    extern __shared__ float sm[];
    float* s_y = sm;              // 64 x LDA : LN1 out (tf32) -> later xf (fp32)
    float* s_b = sm + 16640;      // 64 x LDA : attn out (tf32) -> later y2 (tf32)
    float* s_u = sm + 33280;      // qkv head-pair chunk (LDQ) / FFN hidden chunk (LDA)

    const int tid  = threadIdx.x;
    const int lane = tid & 31;
    const int wid  = tid >> 5;
    const int g    = lane >> 2;     // 0..7
    const int t4   = lane & 3;      // 0..3
    const int wm   = wid & 1;       // M half
    const int wn   = wid >> 1;      // N quarter (0..3)
    const int m_base = wm * 32;
    const int n0   = blockIdx.x * 2;   // first sequence index

    // ---- LN1 directly from gmem -> s_y ----
    for (int rr = wid; rr < 50; rr += 8) {
        int seq = (rr >= 25);
        int tok = rr - seq * 25;
        int r   = seq * 32 + tok;
        const float* xr = x + ((size_t)(n0 + seq) * VTOK + tok) * DM;
        ln_row(xr, s_y + r * LDA, ln1_g, ln1_b, lane);
    }
    __syncthreads();

    // ---- per head-pair: QKV chunk GEMM then attention ----
    for (int it = 0; it < 4; it++) {
        {   // QKV: A = s_y (64x256), B cols = {q,k,v} x {head 2it, 2it+1}, N=192
            float acc[2][6][4];
            #pragma unroll
            for (int mt = 0; mt < 2; mt++)
                #pragma unroll
                for (int nt = 0; nt < 6; nt++)
                    #pragma unroll
                    for (int e = 0; e < 4; e++) acc[mt][nt][e] = 0.f;
            const int cb = wn * 48;
            int gcb[6];
            #pragma unroll
            for (int nt = 0; nt < 6; nt++) {
                int j = cb + nt * 8;
                gcb[nt] = ((j >> 6) << 8) + ((2 * it + ((j & 63) >> 5)) << 5) + (j & 31);
            }
            gemm_sg<6, 256>(s_y + m_base * LDA, g_wr + QKV_OFF, 768, gcb, acc, g, t4);
            #pragma unroll
            for (int mt = 0; mt < 2; mt++) {
                int r = m_base + mt * 16 + g;
                #pragma unroll
                for (int nt = 0; nt < 6; nt++) {
                    int j = cb + nt * 8 + 2 * t4;
                    float bb0 = qkv_b[gcb[nt] + 2 * t4];
                    float bb1 = qkv_b[gcb[nt] + 2 * t4 + 1];
                    s_u[r * LDQ + j]           = acc[mt][nt][0] + bb0;
                    s_u[r * LDQ + j + 1]       = acc[mt][nt][1] + bb1;
                    s_u[(r + 8) * LDQ + j]     = acc[mt][nt][2] + bb0;
                    s_u[(r + 8) * LDQ + j + 1] = acc[mt][nt][3] + bb1;
                }
            }
        }
        __syncthreads();

        if (wid < 4) {  // attention: warp = (seq, head-in-pair)
            const int s  = wid >> 1, hh = wid & 1, h = 2 * it + hh;
            const int i  = lane;
            const int ri = (i < VTOK) ? i : 0;
            const float* base = s_u + (s * 32) * LDQ;
            const float* qb = base + hh * 32;
            const float* kb = base + 64 + hh * 32;
            const float* vb = base + 128 + hh * 32;

            float q[HD];
            #pragma unroll
            for (int d = 0; d < HD; d++) q[d] = qb[ri * LDQ + d];
            float qn2 = 0.f, kn2 = 0.f;
            #pragma unroll
            for (int d = 0; d < HD; d++) qn2 = fmaf(q[d], q[d], qn2);
            #pragma unroll
            for (int d = 0; d < HD; d++) { float kv = kb[ri * LDQ + d]; kn2 = fmaf(kv, kv, kn2); }
            float inv_kn = 1.f / fmaxf(sqrtf(kn2), 1e-12f);

            float sc   = expf(fminf(logit_scale[h], 4.6051701859880913680f));
            float coef = sc * (1.f / fmaxf(sqrtf(qn2), 1e-12f)) * 0.17677669529663688110f;

            float lg[VTOK];
            #pragma unroll
            for (int j = 0; j < VTOK; j++) {
                float ikn = __shfl_sync(0xffffffffu, inv_kn, j);
                float dot = 0.f;
                #pragma unroll
                for (int d = 0; d < HD; d++) dot = fmaf(q[d], kb[j * LDQ + d], dot);
                lg[j] = dot * coef * ikn;
            }
            float m = lg[0];
            #pragma unroll
            for (int j = 1; j < VTOK; j++) m = fmaxf(m, lg[j]);
            float ssum = 0.f;
            #pragma unroll
            for (int j = 0; j < VTOK; j++) { lg[j] = expf(lg[j] - m); ssum += lg[j]; }
            float rs = 1.f / ssum;

            float o[HD];
            #pragma unroll
            for (int d = 0; d < HD; d++) o[d] = 0.f;
            #pragma unroll
            for (int j = 0; j < VTOK; j++) {
                float p = lg[j] * rs;
                #pragma unroll
                for (int d = 0; d < HD; d++) o[d] = fmaf(p, vb[j * LDQ + d], o[d]);
            }
            if (i < VTOK) {
                #pragma unroll
                for (int d = 0; d < HD; d++)
                    s_b[(s * 32 + i) * LDA + h * 32 + d] = tf32r(o[d]);
            }
        }
        __syncthreads();
    }

    // ---- proj + residual: xf = x + attnout @ W + b -> s_y (fp32) ----
    {
        const int cb8 = wn * 64;
        float acc[2][8][4];
        #pragma unroll
        for (int mt = 0; mt < 2; mt++)
            #pragma unroll
            for (int nt = 0; nt < 8; nt++)
                #pragma unroll
                for (int e = 0; e < 4; e++) acc[mt][nt][e] = 0.f;
        int coff[8];
        #pragma unroll
        for (int nt = 0; nt < 8; nt++) coff[nt] = nt * 8;
        gemm_sg<8, 256>(s_b + m_base * LDA, g_wr + PROJ_OFF + cb8, 256, coff, acc, g, t4);
        #pragma unroll
        for (int mt = 0; mt < 2; mt++) {
            int rb = m_base + mt * 16 + g;
            #pragma unroll
            for (int nt = 0; nt < 8; nt++) {
                int c = cb8 + nt * 8 + 2 * t4;
                float pb0 = proj_b[c], pb1 = proj_b[c + 1];
                #pragma unroll
                for (int hrow = 0; hrow < 2; hrow++) {
                    int r = rb + hrow * 8;
                    int tok = r & 31;
                    if (tok < VTOK) {
                        size_t gx = ((size_t)(n0 + (r >> 5)) * VTOK + tok) * DM + c;
                        float2 xv = *(const float2*)(x + gx);
                        s_y[r * LDA + c]     = xv.x + acc[mt][nt][2 * hrow]     + pb0;
                        s_y[r * LDA + c + 1] = xv.y + acc[mt][nt][2 * hrow + 1] + pb1;
                    }
                }
            }
        }
    }
    __syncthreads();

    // ---- LN2: s_y (xf) -> s_b (y2, tf32) ----
    for (int rr = wid; rr < 50; rr += 8) {
        int seq = (rr >= 25);
        int tok = rr - seq * 25;
        int r   = seq * 32 + tok;
        ln_row(s_y + r * LDA, s_b + r * LDA, ln2_g, ln2_b, lane);
    }
    __syncthreads();

    // ---- FFN: 8 hidden chunks of 128; FFN2 accumulates in regs ----
    {
        const int cb8 = wn * 64;     // out cols per warp (FFN2)
        const int cb4 = wn * 32;     // hidden cols per warp (FFN1)
        float oacc[2][8][4];
        #pragma unroll
        for (int mt = 0; mt < 2; mt++)
            #pragma unroll
            for (int nt = 0; nt < 8; nt++)
                #pragma unroll
                for (int e = 0; e < 4; e++) oacc[mt][nt][e] = 0.f;
        int coff8[8], coff4[4];
        #pragma unroll
        for (int nt = 0; nt < 8; nt++) coff8[nt] = nt * 8;
        #pragma unroll
        for (int nt = 0; nt < 4; nt++) coff4[nt] = nt * 8;

        for (int cc = 0; cc < 8; cc++) {
            float hacc[2][4][4];
            #pragma unroll
            for (int mt = 0; mt < 2; mt++)
                #pragma unroll
                for (int nt = 0; nt < 4; nt++)
                    #pragma unroll
                    for (int e = 0; e < 4; e++) hacc[mt][nt][e] = 0.f;
            gemm_sg<4, 256>(s_b + m_base * LDA, g_wr + F1_OFF + cc * 128 + cb4, DF,
                            coff4, hacc, g, t4);
            #pragma unroll
            for (int mt = 0; mt < 2; mt++) {
                int r = m_base + mt * 16 + g;
                #pragma unroll
                for (int nt = 0; nt < 4; nt++) {
                    int cl = cb4 + nt * 8 + 2 * t4;
                    float b10 = ffn_b1[cc * 128 + cl], b11 = ffn_b1[cc * 128 + cl + 1];
                    s_u[r * LDA + cl]           = tf32r(gelu_exact(hacc[mt][nt][0] + b10));
                    s_u[r * LDA + cl + 1]       = tf32r(gelu_exact(hacc[mt][nt][1] + b11));
                    s_u[(r + 8) * LDA + cl]     = tf32r(gelu_exact(hacc[mt][nt][2] + b10));
                    s_u[(r + 8) * LDA + cl + 1] = tf32r(gelu_exact(hacc[mt][nt][3] + b11));
                }
            }
            __syncthreads();
            gemm_sg<8, 128>(s_u + m_base * LDA, g_wr + F2_OFF + (size_t)cc * 128 * 256 + cb8, 256,
                            coff8, oacc, g, t4);
            __syncthreads();
        }

        // ---- final: out = xf + ffn + b2 ----
        #pragma unroll
        for (int mt = 0; mt < 2; mt++) {
            int rb = m_base + mt * 16 + g;
            #pragma unroll
            for (int nt = 0; nt < 8; nt++) {
                int c = cb8 + nt * 8 + 2 * t4;
                float b20 = ffn_b2[c], b21 = ffn_b2[c + 1];
                #pragma unroll
                for (int hrow = 0; hrow < 2; hrow++) {
                    int r = rb + hrow * 8;
                    int tok = r & 31;
                    if (tok < VTOK) {
                        size_t go = ((size_t)(n0 + (r >> 5)) * VTOK + tok) * DM + c;
                        float2 o;
                        o.x = s_y[r * LDA + c]     + oacc[mt][nt][2 * hrow]     + b20;
                        o.y = s_y[r * LDA + c + 1] + oacc[mt][nt][2 * hrow + 1] + b21;
                        *(float2*)(out + go) = o;
                    }
                }
            }
        }
    }
}

extern "C" void kernel_launch(void* const* d_in, const int* in_sizes, int n_in,
                              void* d_out, int out_size)
{
    const float* x      = (const float*)d_in[0];
    const float* ln1_g  = (const float*)d_in[1];
    const float* ln1_b  = (const float*)d_in[2];
    const float* qkv_w  = (const float*)d_in[3];
    const float* qkv_b  = (const float*)d_in[4];
    const float* proj_w = (const float*)d_in[5];
    const float* proj_b = (const float*)d_in[6];
    const float* lscale = (const float*)d_in[7];
    const float* ln2_g  = (const float*)d_in[8];
    const float* ln2_b  = (const float*)d_in[9];
    const float* ffn_w1 = (const float*)d_in[10];
    const float* ffn_b1 = (const float*)d_in[11];
    const float* ffn_w2 = (const float*)d_in[12];
    const float* ffn_b2 = (const float*)d_in[13];
    float* out = (float*)d_out;

    prep_kernel<<<(WTOT + 255) / 256, 256>>>(qkv_w, proj_w, ffn_w1, ffn_w2);

    size_t smem = 49920 * sizeof(float);   // 199680 B
    cudaFuncSetAttribute(spatial_block_mma,
                         cudaFuncAttributeMaxDynamicSharedMemorySize, (int)smem);
    spatial_block_mma<<<NCTA, 256, smem>>>(
        x, ln1_g, ln1_b, qkv_b, proj_b, lscale,
        ln2_g, ln2_b, ffn_b1, ffn_b2, out);
}

// round 5
// speedup vs baseline: 4.1670x; 1.6596x over previous
#include <cuda_runtime.h>
#include <math.h>
#include <stdint.h>

#define NSEQ  8192
#define VTOK  25
#define DM    256
#define NH    8
#define HD    32
#define DF    1024
#define LDA   260          // padded row stride for GEMM-A smem buffers (conflict-free frags)
#define LDQ   196          // row stride for qkv head-pair chunk buffer
#define NCTA  (NSEQ/2)

// packed fragment weights: [tile][kb][lane][4]  (float4 per lane per 16-k block)
#define QKV_OFF  0
#define PROJ_OFF 196608
#define F1_OFF   262144
#define F2_OFF   524288
#define WTOT     786432

__device__ float g_wr[WTOT];   // tf32-rounded, fragment-packed weights

__device__ __forceinline__ float tf32r(float x) {
    uint32_t u; asm("cvt.rna.tf32.f32 %0, %1;" : "=r"(u) : "f"(x));
    return __uint_as_float(u);
}
__device__ __forceinline__ float gelu_exact(float v) {
    return 0.5f * v * (1.f + erff(v * 0.70710678118654752440f));
}

// Pack weights into MMA-fragment order.
// Element i: e = i&3, lane = (i>>2)&31, g = lane>>2, t4 = lane&3.
// Within a 16-k block, row = t4 + ((e&1)<<2) + ((e>>1)<<3):
//   e0 -> b0 of kstep0 (row t4), e1 -> b1 of kstep0 (row t4+4),
//   e2 -> b0 of kstep1 (row t4+8), e3 -> b1 of kstep1 (row t4+12).
__global__ void prep_pack(const float* __restrict__ qkv_w, const float* __restrict__ proj_w,
                          const float* __restrict__ f1,    const float* __restrict__ f2) {
    int i = blockIdx.x * 256 + threadIdx.x;
    if (i >= WTOT) return;
    int e = i & 3, lane = (i >> 2) & 31, g = lane >> 2, t4 = lane & 3;
    int rk = t4 + ((e & 1) << 2) + ((e >> 1) << 3);
    float v;
    if (i < PROJ_OFF) {              // QKV: [tile 96 = it*24+nb][kb 16][lane][4], N remapped
        int kb = (i >> 7) & 15, tile = i >> 11;
        int it = tile / 24, nb = tile % 24;
        int j = nb * 8 + g;          // chunk-local col 0..191
        int col = ((j >> 6) << 8) + ((2 * it + ((j & 63) >> 5)) << 5) + (j & 31);
        v = qkv_w[(size_t)(kb * 16 + rk) * 768 + col];
    } else if (i < F1_OFF) {         // proj: [tile 32][kb 16]
        int li = i - PROJ_OFF;
        int kb = (li >> 7) & 15, tile = li >> 11;
        v = proj_w[(size_t)(kb * 16 + rk) * 256 + tile * 8 + g];
    } else if (i < F2_OFF) {         // ffn1: [nb 128][kb 16]
        int li = i - F1_OFF;
        int kb = (li >> 7) & 15, nb = li >> 11;
        v = f1[(size_t)(kb * 16 + rk) * 1024 + nb * 8 + g];
    } else {                         // ffn2: [tile 256 = cc*32+nb][kb 8]
        int li = i - F2_OFF;
        int kb = (li >> 7) & 7, tile = li >> 10;
        int nb = tile & 31, cc = tile >> 5;
        v = f2[(size_t)(cc * 128 + kb * 16 + rk) * 256 + nb * 8 + g];
    }
    g_wr[i] = tf32r(v);
}

#define MMA_TF32(D, A, B0, B1)                                              \
    asm("mma.sync.aligned.m16n8k8.row.col.f32.tf32.tf32.f32 "               \
        "{%0,%1,%2,%3}, {%4,%5,%6,%7}, {%8,%9}, {%0,%1,%2,%3};"             \
        : "+f"(D[0]), "+f"(D[1]), "+f"(D[2]), "+f"(D[3])                    \
        : "r"(A[0]), "r"(A[1]), "r"(A[2]), "r"(A[3]), "r"(B0), "r"(B1))

// Warp computes a 32 x NT*8 C tile. A from smem (stride LDA); B from packed gmem
// (one LDG.128 per tile per 16-k block), register double-buffered.
template<int NT, int KB>
__device__ __forceinline__ void gemm_pk(const float* __restrict__ Asm,
                                        const float4* __restrict__ Bp,
                                        const int (&tadd)[NT],   // tile*KB precomputed
                                        float (&acc)[2][NT][4], int lane, int g, int t4)
{
    const float* a0p = Asm + g * LDA + t4;
    const float* a1p = Asm + (16 + g) * LDA + t4;
    float4 bc[NT], bn[NT];
    #pragma unroll
    for (int nt = 0; nt < NT; nt++) bc[nt] = Bp[tadd[nt] * 32 + lane];
    #pragma unroll
    for (int kb = 0; kb < KB; kb++) {
        if (kb < KB - 1) {
            #pragma unroll
            for (int nt = 0; nt < NT; nt++) bn[nt] = Bp[(tadd[nt] + kb + 1) * 32 + lane];
        }
        const int k0 = kb * 16;
        uint32_t a0[4], a1[4], c0[4], c1[4];
        a0[0] = __float_as_uint(a0p[k0]);      a0[1] = __float_as_uint(a0p[8 * LDA + k0]);
        a0[2] = __float_as_uint(a0p[k0 + 4]);  a0[3] = __float_as_uint(a0p[8 * LDA + k0 + 4]);
        a1[0] = __float_as_uint(a1p[k0]);      a1[1] = __float_as_uint(a1p[8 * LDA + k0]);
        a1[2] = __float_as_uint(a1p[k0 + 4]);  a1[3] = __float_as_uint(a1p[8 * LDA + k0 + 4]);
        c0[0] = __float_as_uint(a0p[k0 + 8]);  c0[1] = __float_as_uint(a0p[8 * LDA + k0 + 8]);
        c0[2] = __float_as_uint(a0p[k0 + 12]); c0[3] = __float_as_uint(a0p[8 * LDA + k0 + 12]);
        c1[0] = __float_as_uint(a1p[k0 + 8]);  c1[1] = __float_as_uint(a1p[8 * LDA + k0 + 8]);
        c1[2] = __float_as_uint(a1p[k0 + 12]); c1[3] = __float_as_uint(a1p[8 * LDA + k0 + 12]);
        #pragma unroll
        for (int nt = 0; nt < NT; nt++) {
            uint32_t b0 = __float_as_uint(bc[nt].x), b1 = __float_as_uint(bc[nt].y);
            uint32_t b2 = __float_as_uint(bc[nt].z), b3 = __float_as_uint(bc[nt].w);
            MMA_TF32(acc[0][nt], a0, b0, b1);
            MMA_TF32(acc[1][nt], a1, b0, b1);
            MMA_TF32(acc[0][nt], c0, b2, b3);
            MMA_TF32(acc[1][nt], c1, b2, b3);
        }
        if (kb < KB - 1) {
            #pragma unroll
            for (int nt = 0; nt < NT; nt++) bc[nt] = bn[nt];
        }
    }
}

__device__ __forceinline__ void ln_row(const float* __restrict__ src, float* __restrict__ dst,
                                       const float* __restrict__ gg, const float* __restrict__ bb,
                                       int lane)
{
    float v[8], s = 0.f, s2 = 0.f;
    #pragma unroll
    for (int j = 0; j < 8; j++) { v[j] = src[lane + 32 * j]; s += v[j]; s2 += v[j] * v[j]; }
    #pragma unroll
    for (int o = 16; o > 0; o >>= 1) {
        s  += __shfl_xor_sync(0xffffffffu, s,  o);
        s2 += __shfl_xor_sync(0xffffffffu, s2, o);
    }
    float mean = s * (1.f / DM);
    float var  = s2 * (1.f / DM) - mean * mean;
    float inv  = rsqrtf(var + 1e-5f);
    #pragma unroll
    for (int j = 0; j < 8; j++) {
        int c = lane + 32 * j;
        dst[c] = tf32r((v[j] - mean) * inv * gg[c] + bb[c]);
    }
}

__global__ __launch_bounds__(256, 1)
void spatial_block_mma(
    const float* __restrict__ x,
    const float* __restrict__ ln1_g, const float* __restrict__ ln1_b,
    const float* __restrict__ qkv_b,
    const float* __restrict__ proj_b,
    const float* __restrict__ logit_scale,
    const float* __restrict__ ln2_g, const float* __restrict__ ln2_b,
    const float* __restrict__ ffn_b1, const float* __restrict__ ffn_b2,
    float* __restrict__ out)
{
    extern __shared__ float sm[];
    float* s_y = sm;              // 64 x LDA : LN1 out (tf32) -> later xf (fp32)
    float* s_b = sm + 16640;      // 64 x LDA : attn out (tf32) -> later y2 (tf32)
    float* s_u = sm + 33280;      // qkv head-pair chunk (LDQ) / FFN hidden chunk (LDA)

    const int tid  = threadIdx.x;
    const int lane = tid & 31;
    const int wid  = tid >> 5;
    const int g    = lane >> 2;     // 0..7
    const int t4   = lane & 3;      // 0..3
    const int wm   = wid & 1;       // M half
    const int wn   = wid >> 1;      // N quarter (0..3)
    const int m_base = wm * 32;
    const int n0   = blockIdx.x * 2;   // first sequence index

    // ---- LN1 directly from gmem -> s_y ----
    for (int rr = wid; rr < 50; rr += 8) {
        int seq = (rr >= 25);
        int tok = rr - seq * 25;
        int r   = seq * 32 + tok;
        const float* xr = x + ((size_t)(n0 + seq) * VTOK + tok) * DM;
        ln_row(xr, s_y + r * LDA, ln1_g, ln1_b, lane);
    }
    __syncthreads();

    // ---- per head-pair: QKV chunk GEMM then attention ----
    for (int it = 0; it < 4; it++) {
        {   // QKV: A = s_y (64x256), B tiles = packed chunk [it], N=192
            float acc[2][6][4];
            #pragma unroll
            for (int mt = 0; mt < 2; mt++)
                #pragma unroll
                for (int nt = 0; nt < 6; nt++)
                    #pragma unroll
                    for (int e = 0; e < 4; e++) acc[mt][nt][e] = 0.f;
            const int cb = wn * 48;
            int tadd[6], gcb[6];
            #pragma unroll
            for (int nt = 0; nt < 6; nt++) {
                tadd[nt] = (it * 24 + wn * 6 + nt) * 16;
                int j = cb + nt * 8;
                gcb[nt] = ((j >> 6) << 8) + ((2 * it + ((j & 63) >> 5)) << 5) + (j & 31);
            }
            gemm_pk<6, 16>(s_y + m_base * LDA, (const float4*)(g_wr + QKV_OFF),
                           tadd, acc, lane, g, t4);
            #pragma unroll
            for (int mt = 0; mt < 2; mt++) {
                int r = m_base + mt * 16 + g;
                #pragma unroll
                for (int nt = 0; nt < 6; nt++) {
                    int j = cb + nt * 8 + 2 * t4;
                    float bb0 = qkv_b[gcb[nt] + 2 * t4];
                    float bb1 = qkv_b[gcb[nt] + 2 * t4 + 1];
                    s_u[r * LDQ + j]           = acc[mt][nt][0] + bb0;
                    s_u[r * LDQ + j + 1]       = acc[mt][nt][1] + bb1;
                    s_u[(r + 8) * LDQ + j]     = acc[mt][nt][2] + bb0;
                    s_u[(r + 8) * LDQ + j + 1] = acc[mt][nt][3] + bb1;
                }
            }
        }
        __syncthreads();

        if (wid < 4) {  // attention: warp = (seq, head-in-pair)
            const int s  = wid >> 1, hh = wid & 1, h = 2 * it + hh;
            const int i  = lane;
            const int ri = (i < VTOK) ? i : 0;
            const float* base = s_u + (s * 32) * LDQ;
            const float* qb = base + hh * 32;
            const float* kb = base + 64 + hh * 32;
            const float* vb = base + 128 + hh * 32;

            float q[HD];
            #pragma unroll
            for (int d = 0; d < HD; d++) q[d] = qb[ri * LDQ + d];
            float qn2 = 0.f, kn2 = 0.f;
            #pragma unroll
            for (int d = 0; d < HD; d++) qn2 = fmaf(q[d], q[d], qn2);
            #pragma unroll
            for (int d = 0; d < HD; d++) { float kv = kb[ri * LDQ + d]; kn2 = fmaf(kv, kv, kn2); }
            float inv_kn = 1.f / fmaxf(sqrtf(kn2), 1e-12f);

            float sc   = expf(fminf(logit_scale[h], 4.6051701859880913680f));
            float coef = sc * (1.f / fmaxf(sqrtf(qn2), 1e-12f)) * 0.17677669529663688110f;

            float lg[VTOK];
            #pragma unroll
            for (int j = 0; j < VTOK; j++) {
                float ikn = __shfl_sync(0xffffffffu, inv_kn, j);
                float dot = 0.f;
                #pragma unroll
                for (int d = 0; d < HD; d++) dot = fmaf(q[d], kb[j * LDQ + d], dot);
                lg[j] = dot * coef * ikn;
            }
            float m = lg[0];
            #pragma unroll
            for (int j = 1; j < VTOK; j++) m = fmaxf(m, lg[j]);
            float ssum = 0.f;
            #pragma unroll
            for (int j = 0; j < VTOK; j++) { lg[j] = expf(lg[j] - m); ssum += lg[j]; }
            float rs = 1.f / ssum;

            float o[HD];
            #pragma unroll
            for (int d = 0; d < HD; d++) o[d] = 0.f;
            #pragma unroll
            for (int j = 0; j < VTOK; j++) {
                float p = lg[j] * rs;
                #pragma unroll
                for (int d = 0; d < HD; d++) o[d] = fmaf(p, vb[j * LDQ + d], o[d]);
            }
            if (i < VTOK) {
                #pragma unroll
                for (int d = 0; d < HD; d++)
                    s_b[(s * 32 + i) * LDA + h * 32 + d] = tf32r(o[d]);
            }
        }
        __syncthreads();
    }

    // ---- proj + residual: xf = x + attnout @ W + b -> s_y (fp32) ----
    {
        const int cb8 = wn * 64;
        float acc[2][8][4];
        #pragma unroll
        for (int mt = 0; mt < 2; mt++)
            #pragma unroll
            for (int nt = 0; nt < 8; nt++)
                #pragma unroll
                for (int e = 0; e < 4; e++) acc[mt][nt][e] = 0.f;
        int tadd[8];
        #pragma unroll
        for (int nt = 0; nt < 8; nt++) tadd[nt] = (wn * 8 + nt) * 16;
        gemm_pk<8, 16>(s_b + m_base * LDA, (const float4*)(g_wr + PROJ_OFF),
                       tadd, acc, lane, g, t4);
        #pragma unroll
        for (int mt = 0; mt < 2; mt++) {
            int rb = m_base + mt * 16 + g;
            #pragma unroll
            for (int nt = 0; nt < 8; nt++) {
                int c = cb8 + nt * 8 + 2 * t4;
                float pb0 = proj_b[c], pb1 = proj_b[c + 1];
                #pragma unroll
                for (int hrow = 0; hrow < 2; hrow++) {
                    int r = rb + hrow * 8;
                    int tok = r & 31;
                    if (tok < VTOK) {
                        size_t gx = ((size_t)(n0 + (r >> 5)) * VTOK + tok) * DM + c;
                        float2 xv = *(const float2*)(x + gx);
                        s_y[r * LDA + c]     = xv.x + acc[mt][nt][2 * hrow]     + pb0;
                        s_y[r * LDA + c + 1] = xv.y + acc[mt][nt][2 * hrow + 1] + pb1;
                    }
                }
            }
        }
    }
    __syncthreads();

    // ---- LN2: s_y (xf) -> s_b (y2, tf32) ----
    for (int rr = wid; rr < 50; rr += 8) {
        int seq = (rr >= 25);
        int tok = rr - seq * 25;
        int r   = seq * 32 + tok;
        ln_row(s_y + r * LDA, s_b + r * LDA, ln2_g, ln2_b, lane);
    }
    __syncthreads();

    // ---- FFN: 8 hidden chunks of 128; FFN2 accumulates in regs ----
    {
        const int cb8 = wn * 64;     // out cols per warp (FFN2)
        const int cb4 = wn * 32;     // hidden cols per warp (FFN1)
        float oacc[2][8][4];
        #pragma unroll
        for (int mt = 0; mt < 2; mt++)
            #pragma unroll
            for (int nt = 0; nt < 8; nt++)
                #pragma unroll
                for (int e = 0; e < 4; e++) oacc[mt][nt][e] = 0.f;

        for (int cc = 0; cc < 8; cc++) {
            float hacc[2][4][4];
            #pragma unroll
            for (int mt = 0; mt < 2; mt++)
                #pragma unroll
                for (int nt = 0; nt < 4; nt++)
                    #pragma unroll
                    for (int e = 0; e < 4; e++) hacc[mt][nt][e] = 0.f;
            int tadd4[4];
            #pragma unroll
            for (int nt = 0; nt < 4; nt++) tadd4[nt] = (cc * 16 + wn * 4 + nt) * 16;
            gemm_pk<4, 16>(s_b + m_base * LDA, (const float4*)(g_wr + F1_OFF),
                           tadd4, hacc, lane, g, t4);
            #pragma unroll
            for (int mt = 0; mt < 2; mt++) {
                int r = m_base + mt * 16 + g;
                #pragma unroll
                for (int nt = 0; nt < 4; nt++) {
                    int cl = cb4 + nt * 8 + 2 * t4;
                    float b10 = ffn_b1[cc * 128 + cl], b11 = ffn_b1[cc * 128 + cl + 1];
                    s_u[r * LDA + cl]           = tf32r(gelu_exact(hacc[mt][nt][0] + b10));
                    s_u[r * LDA + cl + 1]       = tf32r(gelu_exact(hacc[mt][nt][1] + b11));
                    s_u[(r + 8) * LDA + cl]     = tf32r(gelu_exact(hacc[mt][nt][2] + b10));
                    s_u[(r + 8) * LDA + cl + 1] = tf32r(gelu_exact(hacc[mt][nt][3] + b11));
                }
            }
            __syncthreads();
            int tadd8[8];
            #pragma unroll
            for (int nt = 0; nt < 8; nt++) tadd8[nt] = (cc * 32 + wn * 8 + nt) * 8;
            gemm_pk<8, 8>(s_u + m_base * LDA, (const float4*)(g_wr + F2_OFF),
                          tadd8, oacc, lane, g, t4);
            __syncthreads();
        }

        // ---- final: out = xf + ffn + b2 ----
        #pragma unroll
        for (int mt = 0; mt < 2; mt++) {
            int rb = m_base + mt * 16 + g;
            #pragma unroll
            for (int nt = 0; nt < 8; nt++) {
                int c = cb8 + nt * 8 + 2 * t4;
                float b20 = ffn_b2[c], b21 = ffn_b2[c + 1];
                #pragma unroll
                for (int hrow = 0; hrow < 2; hrow++) {
                    int r = rb + hrow * 8;
                    int tok = r & 31;
                    if (tok < VTOK) {
                        size_t go = ((size_t)(n0 + (r >> 5)) * VTOK + tok) * DM + c;
                        float2 o;
                        o.x = s_y[r * LDA + c]     + oacc[mt][nt][2 * hrow]     + b20;
                        o.y = s_y[r * LDA + c + 1] + oacc[mt][nt][2 * hrow + 1] + b21;
                        *(float2*)(out + go) = o;
                    }
                }
            }
        }
    }
}

extern "C" void kernel_launch(void* const* d_in, const int* in_sizes, int n_in,
                              void* d_out, int out_size)
{
    const float* x      = (const float*)d_in[0];
    const float* ln1_g  = (const float*)d_in[1];
    const float* ln1_b  = (const float*)d_in[2];
    const float* qkv_w  = (const float*)d_in[3];
    const float* qkv_b  = (const float*)d_in[4];
    const float* proj_w = (const float*)d_in[5];
    const float* proj_b = (const float*)d_in[6];
    const float* lscale = (const float*)d_in[7];
    const float* ln2_g  = (const float*)d_in[8];
    const float* ln2_b  = (const float*)d_in[9];
    const float* ffn_w1 = (const float*)d_in[10];
    const float* ffn_b1 = (const float*)d_in[11];
    const float* ffn_w2 = (const float*)d_in[12];
    const float* ffn_b2 = (const float*)d_in[13];
    float* out = (float*)d_out;

    prep_pack<<<(WTOT + 255) / 256, 256>>>(qkv_w, proj_w, ffn_w1, ffn_w2);

    size_t smem = 49920 * sizeof(float);   // 199680 B
    cudaFuncSetAttribute(spatial_block_mma,
                         cudaFuncAttributeMaxDynamicSharedMemorySize, (int)smem);
    spatial_block_mma<<<NCTA, 256, smem>>>(
        x, ln1_g, ln1_b, qkv_b, proj_b, lscale,
        ln2_g, ln2_b, ffn_b1, ffn_b2, out);
}

// round 8
// speedup vs baseline: 4.3969x; 1.0552x over previous
#include <cuda_runtime.h>
#include <cuda_bf16.h>
#include <math.h>
#include <stdint.h>

#define NSEQ  8192
#define VTOK  25
#define DM    256
#define NH    8
#define HD    32
#define DF    1024
#define LDH   264     // bf16 A-buffer row stride (halves): 264/8 odd -> conflict-free ldmatrix
#define LDH2  136     // bf16 hidden-buffer row stride (halves)
#define LDA   260     // fp32 xf buffer row stride
#define LDQ   196     // fp32 qkv chunk row stride
#define NCTA  (NSEQ/2)

// packed bf16 fragment weights, uint32 words; [tile][kb32][lane][uint4]
#define WU32      393216
#define PROJ_U32  98304
#define F1_U32    131072
#define F2_U32    262144

__device__ uint32_t g_wb[WU32];

__device__ __forceinline__ float gelu_exact(float v) {
    return 0.5f * v * (1.f + erff(v * 0.70710678118654752440f));
}
__device__ __forceinline__ uint32_t pack_bf2(float lo, float hi) {
    __nv_bfloat162 p;
    p.x = __float2bfloat16_rn(lo);
    p.y = __float2bfloat16_rn(hi);
    return *(uint32_t*)&p;
}

// Pack weights to bf16 MMA-B fragments for m16n8k16.
// uint4 per (tile, kb32, lane): .x={k+2t4,+1}, .y={k+2t4+8,+9}, .z/.w same +16.
__global__ void prep_pack(const float* __restrict__ qkv_w, const float* __restrict__ proj_w,
                          const float* __restrict__ f1,    const float* __restrict__ f2) {
    int i = blockIdx.x * 256 + threadIdx.x;
    if (i >= WU32) return;
    int comp = i & 3, lane = (i >> 2) & 31;
    int g = lane >> 2, t4 = lane & 3;
    int klo = 2 * t4 + ((comp & 1) << 3) + ((comp >> 1) << 4);
    const float* W; int ldw, k, col;
    if (i < PROJ_U32) {                       // QKV: 96 tiles x 8 kb
        int r2 = i >> 7;
        int kb = r2 & 7, tile = r2 >> 3;
        int it = tile / 24, nb = tile % 24;
        int j = nb * 8 + g;
        col = ((j >> 6) << 8) + ((2 * it + ((j & 63) >> 5)) << 5) + (j & 31);
        k = kb * 32 + klo; W = qkv_w; ldw = 768;
    } else if (i < F1_U32) {                  // proj: 32 tiles x 8 kb
        int r2 = (i - PROJ_U32) >> 7;
        int kb = r2 & 7, tile = r2 >> 3;
        col = tile * 8 + g; k = kb * 32 + klo; W = proj_w; ldw = 256;
    } else if (i < F2_U32) {                  // ffn1: 128 tiles x 8 kb
        int r2 = (i - F1_U32) >> 7;
        int kb = r2 & 7, tile = r2 >> 3;
        col = tile * 8 + g; k = kb * 32 + klo; W = f1; ldw = 1024;
    } else {                                  // ffn2: 256 tiles (cc*32+nb) x 4 kb
        int r2 = (i - F2_U32) >> 7;
        int kb = r2 & 3, tile = r2 >> 2;
        int nb = tile & 31, cc = tile >> 5;
        col = nb * 8 + g; k = cc * 128 + kb * 32 + klo; W = f2; ldw = 256;
    }
    g_wb[i] = pack_bf2(W[(size_t)k * ldw + col], W[(size_t)(k + 1) * ldw + col]);
}

#define MMA_BF(D, A, B0, B1)                                                \
    asm("mma.sync.aligned.m16n8k16.row.col.f32.bf16.bf16.f32 "              \
        "{%0,%1,%2,%3}, {%4,%5,%6,%7}, {%8,%9}, {%0,%1,%2,%3};"             \
        : "+f"(D[0]), "+f"(D[1]), "+f"(D[2]), "+f"(D[3])                    \
        : "r"(A[0]), "r"(A[1]), "r"(A[2]), "r"(A[3]), "r"(B0), "r"(B1))

#define LDSM4(A, addr)                                                      \
    asm volatile("ldmatrix.sync.aligned.m8n8.x4.shared.b16 {%0,%1,%2,%3}, [%4];" \
        : "=r"(A[0]), "=r"(A[1]), "=r"(A[2]), "=r"(A[3]) : "r"(addr))

__device__ __forceinline__ uint32_t ldsm_addr(const __nv_bfloat16* base, int ldh, int lane) {
    return (uint32_t)__cvta_generic_to_shared(base + (lane & 15) * ldh + (lane >> 4) * 8);
}

// Warp computes 32 x NT*8 C tile: A bf16 from smem via ldmatrix (2 m16 halves),
// B from packed gmem (one LDG.128 per tile per 32-k), register double-buffered.
template<int NT, int KB>
__device__ __forceinline__ void gemm_bf(uint32_t a0addr, uint32_t a1addr,
                                        const uint4* __restrict__ Bp,
                                        const int (&tadd)[NT],
                                        float (&acc)[2][NT][4], int lane)
{
    uint4 bc[NT], bn[NT];
    #pragma unroll
    for (int nt = 0; nt < NT; nt++) bc[nt] = Bp[tadd[nt] * 32 + lane];
    #pragma unroll
    for (int kb = 0; kb < KB; kb++) {
        if (kb < KB - 1) {
            #pragma unroll
            for (int nt = 0; nt < NT; nt++) bn[nt] = Bp[(tadd[nt] + kb + 1) * 32 + lane];
        }
        uint32_t A0[4], A1[4], A2[4], A3[4];
        LDSM4(A0, a0addr + kb * 64);
        LDSM4(A1, a1addr + kb * 64);
        LDSM4(A2, a0addr + kb * 64 + 32);
        LDSM4(A3, a1addr + kb * 64 + 32);
        #pragma unroll
        for (int nt = 0; nt < NT; nt++) {
            MMA_BF(acc[0][nt], A0, bc[nt].x, bc[nt].y);
            MMA_BF(acc[1][nt], A1, bc[nt].x, bc[nt].y);
            MMA_BF(acc[0][nt], A2, bc[nt].z, bc[nt].w);
            MMA_BF(acc[1][nt], A3, bc[nt].z, bc[nt].w);
        }
        if (kb < KB - 1) {
            #pragma unroll
            for (int nt = 0; nt < NT; nt++) bc[nt] = bn[nt];
        }
    }
}

__device__ __forceinline__ void ln_row_bf(const float* __restrict__ src,
                                          __nv_bfloat16* __restrict__ dst,
                                          const float* __restrict__ gg,
                                          const float* __restrict__ bb, int lane)
{
    float v[8], s = 0.f, s2 = 0.f;
    #pragma unroll
    for (int j = 0; j < 8; j++) { v[j] = src[lane + 32 * j]; s += v[j]; s2 += v[j] * v[j]; }
    #pragma unroll
    for (int o = 16; o > 0; o >>= 1) {
        s  += __shfl_xor_sync(0xffffffffu, s,  o);
        s2 += __shfl_xor_sync(0xffffffffu, s2, o);
    }
    float mean = s * (1.f / DM);
    float var  = s2 * (1.f / DM) - mean * mean;
    float inv  = rsqrtf(var + 1e-5f);
    #pragma unroll
    for (int j = 0; j < 8; j++) {
        int c = lane + 32 * j;
        dst[c] = __float2bfloat16_rn((v[j] - mean) * inv * gg[c] + bb[c]);
    }
}

__global__ __launch_bounds__(256, 1)
void spatial_block_mma(
    const float* __restrict__ x,
    const float* __restrict__ ln1_g, const float* __restrict__ ln1_b,
    const float* __restrict__ qkv_b,
    const float* __restrict__ proj_b,
    const float* __restrict__ logit_scale,
    const float* __restrict__ ln2_g, const float* __restrict__ ln2_b,
    const float* __restrict__ ffn_b1, const float* __restrict__ ffn_b2,
    float* __restrict__ out)
{
    extern __shared__ char smc[];
    __nv_bfloat16* s_yh = (__nv_bfloat16*)smc;                 // 64 x LDH : LN1/LN2 out
    __nv_bfloat16* s_bh = (__nv_bfloat16*)(smc + 33792);       // 64 x LDH : attn out
    float* s_y  = (float*)(smc + 67584);                       // 64 x LDA : xf fp32
    float* s_u  = (float*)(smc + 134144);                      // qkv chunk fp32 (64 x LDQ)
    __nv_bfloat16* s_h0 = (__nv_bfloat16*)(smc + 134144);      // hidden chunk A (union)
    __nv_bfloat16* s_h1 = (__nv_bfloat16*)(smc + 151552);      // hidden chunk B

    const int tid  = threadIdx.x;
    const int lane = tid & 31;
    const int wid  = tid >> 5;
    const int g    = lane >> 2;
    const int t4   = lane & 3;
    const int wm   = wid & 1;
    const int wn   = wid >> 1;
    const int m_base = wm * 32;
    const int n0   = blockIdx.x * 2;

    const uint4* BQ = (const uint4*)g_wb;
    const uint4* BP = (const uint4*)g_wb + PROJ_U32 / 4;
    const uint4* B1 = (const uint4*)g_wb + F1_U32 / 4;
    const uint4* B2 = (const uint4*)g_wb + F2_U32 / 4;

    // ---- LN1 from gmem -> s_yh (bf16) ----
    for (int rr = wid; rr < 50; rr += 8) {
        int seq = (rr >= 25);
        int tok = rr - seq * 25;
        int r   = seq * 32 + tok;
        const float* xr = x + ((size_t)(n0 + seq) * VTOK + tok) * DM;
        ln_row_bf(xr, s_yh + r * LDH, ln1_g, ln1_b, lane);
    }
    __syncthreads();

    const uint32_t aY0 = ldsm_addr(s_yh + m_base * LDH, LDH, lane);
    const uint32_t aY1 = aY0 + 16 * LDH * 2;
    const uint32_t aB0 = ldsm_addr(s_bh + m_base * LDH, LDH, lane);
    const uint32_t aB1 = aB0 + 16 * LDH * 2;

    // ---- per head-pair: QKV chunk GEMM then attention ----
    for (int it = 0; it < 4; it++) {
        {
            float acc[2][6][4];
            #pragma unroll
            for (int mt = 0; mt < 2; mt++)
                #pragma unroll
                for (int nt = 0; nt < 6; nt++)
                    #pragma unroll
                    for (int e = 0; e < 4; e++) acc[mt][nt][e] = 0.f;
            const int cb = wn * 48;
            int tadd[6], gcb[6];
            #pragma unroll
            for (int nt = 0; nt < 6; nt++) {
                tadd[nt] = (it * 24 + wn * 6 + nt) * 8;
                int j = cb + nt * 8;
                gcb[nt] = ((j >> 6) << 8) + ((2 * it + ((j & 63) >> 5)) << 5) + (j & 31);
            }
            gemm_bf<6, 8>(aY0, aY1, BQ, tadd, acc, lane);
            #pragma unroll
            for (int mt = 0; mt < 2; mt++) {
                int r = m_base + mt * 16 + g;
                #pragma unroll
                for (int nt = 0; nt < 6; nt++) {
                    int j = cb + nt * 8 + 2 * t4;
                    float bb0 = qkv_b[gcb[nt] + 2 * t4];
                    float bb1 = qkv_b[gcb[nt] + 2 * t4 + 1];
                    s_u[r * LDQ + j]           = acc[mt][nt][0] + bb0;
                    s_u[r * LDQ + j + 1]       = acc[mt][nt][1] + bb1;
                    s_u[(r + 8) * LDQ + j]     = acc[mt][nt][2] + bb0;
                    s_u[(r + 8) * LDQ + j + 1] = acc[mt][nt][3] + bb1;
                }
            }
        }
        __syncthreads();

        if (wid < 4) {  // attention: warp = (seq, head-in-pair)
            const int s  = wid >> 1, hh = wid & 1, h = 2 * it + hh;
            const int i  = lane;
            const int ri = (i < VTOK) ? i : 0;
            const float* base = s_u + (s * 32) * LDQ;
            const float* qb = base + hh * 32;
            const float* kb = base + 64 + hh * 32;
            const float* vb = base + 128 + hh * 32;

            float q[HD];
            #pragma unroll
            for (int d = 0; d < HD; d++) q[d] = qb[ri * LDQ + d];
            float qn2 = 0.f, kn2 = 0.f;
            #pragma unroll
            for (int d = 0; d < HD; d++) qn2 = fmaf(q[d], q[d], qn2);
            #pragma unroll
            for (int d = 0; d < HD; d++) { float kv = kb[ri * LDQ + d]; kn2 = fmaf(kv, kv, kn2); }
            float inv_kn = 1.f / fmaxf(sqrtf(kn2), 1e-12f);

            float sc   = expf(fminf(logit_scale[h], 4.6051701859880913680f));
            float coef = sc * (1.f / fmaxf(sqrtf(qn2), 1e-12f)) * 0.17677669529663688110f;

            float lg[VTOK];
            #pragma unroll
            for (int j = 0; j < VTOK; j++) {
                float ikn = __shfl_sync(0xffffffffu, inv_kn, j);
                float dot = 0.f;
                #pragma unroll
                for (int d = 0; d < HD; d++) dot = fmaf(q[d], kb[j * LDQ + d], dot);
                lg[j] = dot * coef * ikn;
            }
            float m = lg[0];
            #pragma unroll
            for (int j = 1; j < VTOK; j++) m = fmaxf(m, lg[j]);
            float ssum = 0.f;
            #pragma unroll
            for (int j = 0; j < VTOK; j++) { lg[j] = expf(lg[j] - m); ssum += lg[j]; }
            float rs = 1.f / ssum;

            float o[HD];
            #pragma unroll
            for (int d = 0; d < HD; d++) o[d] = 0.f;
            #pragma unroll
            for (int j = 0; j < VTOK; j++) {
                float p = lg[j] * rs;
                #pragma unroll
                for (int d = 0; d < HD; d++) o[d] = fmaf(p, vb[j * LDQ + d], o[d]);
            }
            if (i < VTOK) {
                #pragma unroll
                for (int d = 0; d < HD; d++)
                    s_bh[(s * 32 + i) * LDH + h * 32 + d] = __float2bfloat16_rn(o[d]);
            }
        }
        __syncthreads();
    }

    // ---- proj + residual: xf = x + attnout @ W + b -> s_y (fp32) ----
    {
        const int cb8 = wn * 64;
        float acc[2][8][4];
        #pragma unroll
        for (int mt = 0; mt < 2; mt++)
            #pragma unroll
            for (int nt = 0; nt < 8; nt++)
                #pragma unroll
                for (int e = 0; e < 4; e++) acc[mt][nt][e] = 0.f;
        int tadd[8];
        #pragma unroll
        for (int nt = 0; nt < 8; nt++) tadd[nt] = (wn * 8 + nt) * 8;
        gemm_bf<8, 8>(aB0, aB1, BP, tadd, acc, lane);
        #pragma unroll
        for (int mt = 0; mt < 2; mt++) {
            int rb = m_base + mt * 16 + g;
            #pragma unroll
            for (int nt = 0; nt < 8; nt++) {
                int c = cb8 + nt * 8 + 2 * t4;
                float pb0 = proj_b[c], pb1 = proj_b[c + 1];
                #pragma unroll
                for (int hrow = 0; hrow < 2; hrow++) {
                    int r = rb + hrow * 8;
                    int tok = r & 31;
                    if (tok < VTOK) {
                        size_t gx = ((size_t)(n0 + (r >> 5)) * VTOK + tok) * DM + c;
                        float2 xv = *(const float2*)(x + gx);
                        s_y[r * LDA + c]     = xv.x + acc[mt][nt][2 * hrow]     + pb0;
                        s_y[r * LDA + c + 1] = xv.y + acc[mt][nt][2 * hrow + 1] + pb1;
                    }
                }
            }
        }
    }
    __syncthreads();

    // ---- LN2: s_y (xf) -> s_yh (y2, bf16) ----
    for (int rr = wid; rr < 50; rr += 8) {
        int seq = (rr >= 25);
        int tok = rr - seq * 25;
        int r   = seq * 32 + tok;
        ln_row_bf(s_y + r * LDA, s_yh + r * LDH, ln2_g, ln2_b, lane);
    }
    __syncthreads();

    // ---- FFN: 8 hidden chunks of 128, hidden double-buffered; FFN2 accumulates ----
    {
        const int cb8 = wn * 64;
        const int cb4 = wn * 32;
        float oacc[2][8][4];
        #pragma unroll
        for (int mt = 0; mt < 2; mt++)
            #pragma unroll
            for (int nt = 0; nt < 8; nt++)
                #pragma unroll
                for (int e = 0; e < 4; e++) oacc[mt][nt][e] = 0.f;

        const uint32_t aH0_0 = ldsm_addr(s_h0 + m_base * LDH2, LDH2, lane);
        const uint32_t aH0_1 = aH0_0 + 16 * LDH2 * 2;
        const uint32_t aH1_0 = ldsm_addr(s_h1 + m_base * LDH2, LDH2, lane);
        const uint32_t aH1_1 = aH1_0 + 16 * LDH2 * 2;

        for (int cc = 0; cc < 8; cc++) {
            __nv_bfloat16* sh = (cc & 1) ? s_h1 : s_h0;
            float hacc[2][4][4];
            #pragma unroll
            for (int mt = 0; mt < 2; mt++)
                #pragma unroll
                for (int nt = 0; nt < 4; nt++)
                    #pragma unroll
                    for (int e = 0; e < 4; e++) hacc[mt][nt][e] = 0.f;
            int tadd4[4];
            #pragma unroll
            for (int nt = 0; nt < 4; nt++) tadd4[nt] = (cc * 16 + wn * 4 + nt) * 8;
            gemm_bf<4, 8>(aY0, aY1, B1, tadd4, hacc, lane);
            #pragma unroll
            for (int mt = 0; mt < 2; mt++) {
                int r = m_base + mt * 16 + g;
                #pragma unroll
                for (int nt = 0; nt < 4; nt++) {
                    int cl = cb4 + nt * 8 + 2 * t4;
                    float b10 = ffn_b1[cc * 128 + cl], b11 = ffn_b1[cc * 128 + cl + 1];
                    *(uint32_t*)(sh + r * LDH2 + cl) =
                        pack_bf2(gelu_exact(hacc[mt][nt][0] + b10), gelu_exact(hacc[mt][nt][1] + b11));
                    *(uint32_t*)(sh + (r + 8) * LDH2 + cl) =
                        pack_bf2(gelu_exact(hacc[mt][nt][2] + b10), gelu_exact(hacc[mt][nt][3] + b11));
                }
            }
            __syncthreads();
            int tadd8[8];
            #pragma unroll
            for (int nt = 0; nt < 8; nt++) tadd8[nt] = (cc * 32 + wn * 8 + nt) * 4;
            if (cc & 1) gemm_bf<8, 4>(aH1_0, aH1_1, B2, tadd8, oacc, lane);
            else        gemm_bf<8, 4>(aH0_0, aH0_1, B2, tadd8, oacc, lane);
        }

        // ---- final: out = xf + ffn + b2 ----
        #pragma unroll
        for (int mt = 0; mt < 2; mt++) {
            int rb = m_base + mt * 16 + g;
            #pragma unroll
            for (int nt = 0; nt < 8; nt++) {
                int c = cb8 + nt * 8 + 2 * t4;
                float b20 = ffn_b2[c], b21 = ffn_b2[c + 1];
                #pragma unroll
                for (int hrow = 0; hrow < 2; hrow++) {
                    int r = rb + hrow * 8;
                    int tok = r & 31;
                    if (tok < VTOK) {
                        size_t go = ((size_t)(n0 + (r >> 5)) * VTOK + tok) * DM + c;
                        float2 o;
                        o.x = s_y[r * LDA + c]     + oacc[mt][nt][2 * hrow]     + b20;
                        o.y = s_y[r * LDA + c + 1] + oacc[mt][nt][2 * hrow + 1] + b21;
                        *(float2*)(out + go) = o;
                    }
                }
            }
        }
    }
}

extern "C" void kernel_launch(void* const* d_in, const int* in_sizes, int n_in,
                              void* d_out, int out_size)
{
    const float* x      = (const float*)d_in[0];
    const float* ln1_g  = (const float*)d_in[1];
    const float* ln1_b  = (const float*)d_in[2];
    const float* qkv_w  = (const float*)d_in[3];
    const float* qkv_b  = (const float*)d_in[4];
    const float* proj_w = (const float*)d_in[5];
    const float* proj_b = (const float*)d_in[6];
    const float* lscale = (const float*)d_in[7];
    const float* ln2_g  = (const float*)d_in[8];
    const float* ln2_b  = (const float*)d_in[9];
    const float* ffn_w1 = (const float*)d_in[10];
    const float* ffn_b1 = (const float*)d_in[11];
    const float* ffn_w2 = (const float*)d_in[12];
    const float* ffn_b2 = (const float*)d_in[13];
    float* out = (float*)d_out;

    prep_pack<<<(WU32 + 255) / 256, 256>>>(qkv_w, proj_w, ffn_w1, ffn_w2);

    size_t smem = 184320;
    cudaFuncSetAttribute(spatial_block_mma,
                         cudaFuncAttributeMaxDynamicSharedMemorySize, (int)smem);
    spatial_block_mma<<<NCTA, 256, smem>>>(
        x, ln1_g, ln1_b, qkv_b, proj_b, lscale,
        ln2_g, ln2_b, ffn_b1, ffn_b2, out);
}